// round 12
// baseline (speedup 1.0000x reference)
#include <cuda_runtime.h>
#include <cuda_fp16.h>
#include <math.h>
#include <stdint.h>

#define NB 8192
#define NE 512
#define NT 32
#define TM 128
#define MAXTILES (NB/TM + NT)        // 96
#define NQ 8                         // N-chunks of 64 per tile
#define MAXCTAS (MAXTILES * NQ)      // 768

// ---------------- device scratch ----------------
__device__ int d_perm[NB];
__device__ int d_tile_tissue[MAXTILES];
__device__ int d_tile_start[MAXTILES];
__device__ int d_tile_rows[MAXTILES];
__device__ int d_ntiles;
__device__ int d_done[MAXTILES];
__device__ float d_part[MAXCTAS * TM];

__device__ __half d_Gh[NB * NE];
__device__ __half d_WhT[(size_t)NT * NE * NE];   // [t][n][k]

// ---------------- PTX helpers (sm_80-level) ----------------
__device__ __forceinline__ uint32_t smem_u32(const void* p) {
    uint32_t a;
    asm("{ .reg .u64 t; cvta.to.shared.u64 t, %1; cvt.u32.u64 %0, t; }"
        : "=r"(a) : "l"(p));
    return a;
}
#define CP16(dst, src) \
    asm volatile("cp.async.cg.shared.global [%0], [%1], 16;" \
                 :: "r"(dst), "l"(src) : "memory")
#define CP_COMMIT() asm volatile("cp.async.commit_group;" ::: "memory")
#define CP_WAIT1()  asm volatile("cp.async.wait_group 1;" ::: "memory")
#define CP_WAIT0()  asm volatile("cp.async.wait_group 0;" ::: "memory")

__device__ __forceinline__ void ldsm4(uint32_t r[4], uint32_t addr) {
    asm volatile("ldmatrix.sync.aligned.m8n8.x4.shared.b16 {%0,%1,%2,%3}, [%4];"
                 : "=r"(r[0]), "=r"(r[1]), "=r"(r[2]), "=r"(r[3]) : "r"(addr));
}
__device__ __forceinline__ void mma16816(float d[4], const uint32_t a[4],
                                         const uint32_t b[2]) {
    asm volatile(
        "mma.sync.aligned.m16n8k16.row.col.f32.f16.f16.f32 "
        "{%0,%1,%2,%3}, {%4,%5,%6,%7}, {%8,%9}, {%0,%1,%2,%3};"
        : "+f"(d[0]), "+f"(d[1]), "+f"(d[2]), "+f"(d[3])
        : "r"(a[0]), "r"(a[1]), "r"(a[2]), "r"(a[3]), "r"(b[0]), "r"(b[1]));
}
__device__ __forceinline__ unsigned pack2h(__half a, __half b) {
    return (unsigned)__half_as_ushort(a) | ((unsigned)__half_as_ushort(b) << 16);
}

// ---------------- ONE prep kernel: group (block 0) | prep_w | prep_g -------
// grid: [0] group, [1..2048] prep_w, [2049..3072] prep_g
#define PREPW_FIRST 1
#define PREPG_FIRST 2049
#define PREP_GRID   3073

__global__ void __launch_bounds__(256)
prep_all(const int* __restrict__ tv32, const float* __restrict__ g,
         const float* __restrict__ W1)
{
    const int bx = blockIdx.x;
    const int tid = threadIdx.x;

    if (bx == 0) {
        // ---- grouping: warp-replicated counters (8 warps x 32 tissues) ----
        __shared__ int s_is64;
        __shared__ int cnt[8][NT];
        __shared__ int cur[8][NT];
        __shared__ int warpor[8];
        const int wgrp = tid >> 5;

        if (tid < MAXTILES) d_done[tid] = 0;
        ((int*)cnt)[tid] = 0;

        int acc = 0;
        for (int i = tid; i < NB / 2; i += 256) acc |= tv32[2 * i + 1];
#pragma unroll
        for (int o = 16; o; o >>= 1) acc |= __shfl_xor_sync(0xFFFFFFFF, acc, o);
        if ((tid & 31) == 0) warpor[wgrp] = acc;
        __syncthreads();
        if (tid == 0) {
            int a = 0;
            for (int i = 0; i < 8; i++) a |= warpor[i];
            s_is64 = (a == 0);
        }
        __syncthreads();
        const int is64 = s_is64;

        // hist into this warp's private counter row
        for (int i = tid; i < NB; i += 256) {
            int t = is64 ? (int)((const long long*)tv32)[i] : tv32[i];
            atomicAdd(&cnt[wgrp][t], 1);
        }
        __syncthreads();
        if (tid == 0) {
            int off = 0, nt = 0;
            for (int t = 0; t < NT; t++) {
                int c = 0;
#pragma unroll
                for (int w = 0; w < 8; w++) c += cnt[w][t];
                int bgs = off;
#pragma unroll
                for (int w = 0; w < 8; w++) { cur[w][t] = bgs; bgs += cnt[w][t]; }
                for (int s = 0; s < c; s += TM) {
                    d_tile_tissue[nt] = t;
                    d_tile_start[nt]  = off + s;
                    d_tile_rows[nt]   = (c - s) < TM ? (c - s) : TM;
                    nt++;
                }
                off += c;
            }
            d_ntiles = nt;
        }
        __syncthreads();
        // scatter using per-warp cursors (same i -> same warp as hist pass)
        for (int i = tid; i < NB; i += 256) {
            int t = is64 ? (int)((const long long*)tv32)[i] : tv32[i];
            int p = atomicAdd(&cur[wgrp][t], 1);
            d_perm[p] = i;
        }
    } else if (bx < PREPG_FIRST) {
        // ---- W transpose + convert: one 64x64 chunk ----
        const int cb = bx - PREPW_FIRST;
        const int t  = cb >> 6;
        const int n0 = ((cb >> 3) & 7) * 64;
        const int k0 = (cb & 7) * 64;
        __shared__ float st[64][65];
        const size_t tb = (size_t)t * NE * NE;
#pragma unroll
        for (int rr = 0; rr < 4; rr++) {
            int idx = tid + rr * 256;
            int k = idx >> 4;
            int nqc = (idx & 15) << 2;
            float4 v = *(const float4*)(W1 + tb + (size_t)(k0 + k) * NE + n0 + nqc);
            st[nqc + 0][k] = v.x; st[nqc + 1][k] = v.y;
            st[nqc + 2][k] = v.z; st[nqc + 3][k] = v.w;
        }
        __syncthreads();
        {
            int n  = tid >> 2;
            int kq = (tid & 3) << 4;
            unsigned hw[8];
#pragma unroll
            for (int j = 0; j < 16; j += 2)
                hw[j >> 1] = pack2h(__float2half_rn(st[n][kq + j]),
                                    __float2half_rn(st[n][kq + j + 1]));
            size_t oo = tb + (size_t)(n0 + n) * NE + k0 + kq;
            *(uint4*)(d_WhT + oo)     = make_uint4(hw[0], hw[1], hw[2], hw[3]);
            *(uint4*)(d_WhT + oo + 8) = make_uint4(hw[4], hw[5], hw[6], hw[7]);
        }
    } else {
        // ---- g convert: 4 independent float4 per thread (MLP 4) ----
        const int base = (bx - PREPG_FIRST) * 1024 + tid;
        float4 v[4];
#pragma unroll
        for (int r = 0; r < 4; r++) v[r] = ((const float4*)g)[base + r * 256];
#pragma unroll
        for (int r = 0; r < 4; r++)
            ((uint2*)d_Gh)[base + r * 256] = make_uint2(
                pack2h(__float2half_rn(v[r].x), __float2half_rn(v[r].y)),
                pack2h(__float2half_rn(v[r].z), __float2half_rn(v[r].w)));
    }
}

// ---------------- mma.sync fused GEMM (M=128, N=64 per CTA, 256 thr) -------
// R8-proven mainloop: K-tile 32, 16 stages. stage buf: A 0..8K | B 8K..12K
#define BUFSZ   12288
#define NSTAGE  3
#define SM_RED  (NSTAGE * BUFSZ)                 // float red[128][2] = 1KB
#define SM_TOTAL (SM_RED + 1024)

__global__ void __launch_bounds__(256, 3)
gemm_mma(const float* __restrict__ b1g, const float* __restrict__ W2g,
         const float* __restrict__ b2g, float* __restrict__ out)
{
    extern __shared__ char smem[];
    const uint32_t ST = smem_u32(smem);
    const int tid = threadIdx.x, lane = tid & 31, wid = tid >> 5;
    const int wm = wid & 3, wn = wid >> 2;

    const int b = blockIdx.x;
    const int tile = b >> 3, nq = b & 7;
    if (tile >= d_ntiles) return;
    const int t = d_tile_tissue[tile];
    const int start = d_tile_start[tile];
    const int rows  = d_tile_rows[tile];

    // A gmem: thread loads row arow (2 chunks)
    const int arow = tid >> 1;
    const int m = arow < rows ? arow : rows - 1;
    const __half* pA = d_Gh + (size_t)d_perm[start + m] * NE;
    // B gmem: thread loads row brow (1 chunk)
    const int brow = tid >> 2;
    const __half* pB = d_WhT + (size_t)t * NE * NE + (size_t)(nq * 64 + brow) * NE;

    // store-side addressing
    const uint32_t stA = ST + (uint32_t)arow * 64;
    const int swsA = (arow >> 1) & 3;
    const int cpA = (tid & 1) * 2;
    const uint32_t stB = ST + 8192u + (uint32_t)brow * 64;
    const int swsB = (brow >> 1) & 3;
    const int cB_st = tid & 3;

    // ldmatrix addressing (proven swizzle math)
    const int rA  = lane & 15;
    const int cbA = lane >> 4;
    const int swA = (rA >> 1) & 3;
    const uint32_t preA = (uint32_t)(wm * 32 + rA) * 64;
    const int rB  = (lane & 7) + ((lane >> 4) & 1) * 8;
    const int cbB = (lane >> 3) & 1;
    const int swB = ((lane & 7) >> 1) & 3;
    const uint32_t preB = 8192u + (uint32_t)(wn * 32 + rB) * 64;

    float acc[2][4][4];
#pragma unroll
    for (int mt = 0; mt < 2; mt++)
#pragma unroll
        for (int j = 0; j < 4; j++)
#pragma unroll
            for (int q = 0; q < 4; q++) acc[mt][j][q] = 0.f;

    auto stage_load = [&](int s) {
        const uint32_t off = (uint32_t)(s % NSTAGE) * BUFSZ;
        const int k0 = s * 32;
#pragma unroll
        for (int c = cpA; c < cpA + 2; c++)
            CP16(stA + off + (uint32_t)((c ^ swsA) << 4), pA + k0 + c * 8);
        CP16(stB + off + (uint32_t)((cB_st ^ swsB) << 4), pB + k0 + cB_st * 8);
    };

    // 3-stage prologue
    stage_load(0); CP_COMMIT();
    stage_load(1); CP_COMMIT();

    for (int s = 0; s < 16; s++) {
        if (s < 15) CP_WAIT1(); else CP_WAIT0();
        __syncthreads();               // publishes stage s; frees buffer (s+2)%3
        if (s < 14) { stage_load(s + 2); CP_COMMIT(); }

        const uint32_t bufA = ST + (uint32_t)(s % NSTAGE) * BUFSZ;
#pragma unroll
        for (int ks = 0; ks < 2; ks++) {
            uint32_t a[2][4];
            const uint32_t cA = (uint32_t)(((2 * ks + cbA) ^ swA) << 4);
#pragma unroll
            for (int mt = 0; mt < 2; mt++)
                ldsm4(a[mt], bufA + preA + mt * 1024 + cA);
            const uint32_t cB = (uint32_t)(((2 * ks + cbB) ^ swB) << 4);
#pragma unroll
            for (int g = 0; g < 2; g++) {
                uint32_t bh[4];
                ldsm4(bh, bufA + preB + (uint32_t)g * 1024 + cB);
#pragma unroll
                for (int mt = 0; mt < 2; mt++) {
                    mma16816(acc[mt][2 * g],     a[mt], bh);
                    mma16816(acc[mt][2 * g + 1], a[mt], bh + 2);
                }
            }
        }
    }

    // fused epilogue: +b1 -> gelu -> *W2 -> partial row sums
    float ya[2][2] = {{0.f, 0.f}, {0.f, 0.f}};
#pragma unroll
    for (int mt = 0; mt < 2; mt++)
#pragma unroll
        for (int j = 0; j < 4; j++) {
            const int n = nq * 64 + wn * 32 + (j >> 1) * 16 + (j & 1) * 8 + 2 * (lane & 3);
            const float b10 = __ldg(&b1g[t * NE + n]);
            const float b11 = __ldg(&b1g[t * NE + n + 1]);
            const float w20 = __ldg(&W2g[t * NE + n]);
            const float w21 = __ldg(&W2g[t * NE + n + 1]);
            float h0 = acc[mt][j][0] + b10;
            float h1 = acc[mt][j][1] + b11;
            float h2 = acc[mt][j][2] + b10;
            float h3 = acc[mt][j][3] + b11;
            const float K = 0.70710678118654752f;
            float g0 = 0.5f * h0 * (1.0f + erff(h0 * K));
            float g1 = 0.5f * h1 * (1.0f + erff(h1 * K));
            float g2 = 0.5f * h2 * (1.0f + erff(h2 * K));
            float g3 = 0.5f * h3 * (1.0f + erff(h3 * K));
            ya[mt][0] = fmaf(g0, w20, fmaf(g1, w21, ya[mt][0]));
            ya[mt][1] = fmaf(g2, w20, fmaf(g3, w21, ya[mt][1]));
        }

    float* red = (float*)(smem + SM_RED);   // [128][2]
#pragma unroll
    for (int mt = 0; mt < 2; mt++)
#pragma unroll
        for (int rr = 0; rr < 2; rr++) {
            float v = ya[mt][rr];
            v += __shfl_xor_sync(0xFFFFFFFF, v, 1);
            v += __shfl_xor_sync(0xFFFFFFFF, v, 2);
            if ((lane & 3) == 0) {
                int r = wm * 32 + mt * 16 + (lane >> 2) + rr * 8;
                red[r * 2 + wn] = v;
            }
        }
    __syncthreads();
    if (tid < TM)
        d_part[b * TM + tid] = red[tid * 2] + red[tid * 2 + 1];
    __syncthreads();

    // --- fused finale: last chunk-CTA of this tile reduces + softplus ---
    __shared__ int slast;
    __threadfence();
    if (tid == 0) {
        int v = atomicAdd(&d_done[tile], 1);
        slast = (v == NQ - 1);
    }
    __syncthreads();
    if (slast) {
        __threadfence();
        if (tid < rows) {
            float sv = 0.f;
#pragma unroll
            for (int q = 0; q < NQ; q++)
                sv += d_part[(tile * NQ + q) * TM + tid];
            sv += __ldg(&b2g[t]);
            float y = fmaxf(sv, 0.f) + log1pf(expf(-fabsf(sv)));
            out[d_perm[start + tid]] = y;
        }
        if (tid == 0) d_done[tile] = 0;     // reset for next graph replay
    }
}

// ---------------- launch ----------------
extern "C" void kernel_launch(void* const* d_in, const int* in_sizes, int n_in,
                              void* d_out, int out_size)
{
    const float* g  = (const float*)d_in[0];
    const void*  tv = d_in[1];
    const float* W1 = (const float*)d_in[2];
    const float* b1 = (const float*)d_in[3];
    const float* W2 = (const float*)d_in[4];
    const float* b2 = (const float*)d_in[5];
    float* out = (float*)d_out;

    cudaFuncSetAttribute(gemm_mma, cudaFuncAttributeMaxDynamicSharedMemorySize, SM_TOTAL);

    prep_all<<<PREP_GRID, 256>>>((const int*)tv, g, W1);
    gemm_mma<<<MAXCTAS, 256, SM_TOTAL>>>(b1, W2, b2, out);
}

// round 13
// speedup vs baseline: 1.2557x; 1.2557x over previous
#include <cuda_runtime.h>
#include <cuda_fp16.h>
#include <math.h>
#include <stdint.h>

#define NB 8192
#define NE 512
#define NT 32
#define TM 128
#define MAXTILES (NB/TM + NT)        // 96
#define NQ 8                         // N-chunks of 64 per tile
#define MAXCTAS (MAXTILES * NQ)      // 768

// ---------------- device scratch ----------------
__device__ int d_perm[NB];
__device__ int d_tile_tissue[MAXTILES];
__device__ int d_tile_start[MAXTILES];
__device__ int d_tile_rows[MAXTILES];
__device__ int d_ntiles;
__device__ float d_part[MAXCTAS * TM];

__device__ __half d_Gh[NB * NE];
__device__ __half d_WhT[(size_t)NT * NE * NE];   // [t][n][k]

// ---------------- PTX helpers (sm_80-level) ----------------
__device__ __forceinline__ uint32_t smem_u32(const void* p) {
    uint32_t a;
    asm("{ .reg .u64 t; cvta.to.shared.u64 t, %1; cvt.u32.u64 %0, t; }"
        : "=r"(a) : "l"(p));
    return a;
}
#define CP16(dst, src) \
    asm volatile("cp.async.cg.shared.global [%0], [%1], 16;" \
                 :: "r"(dst), "l"(src) : "memory")
#define CP_COMMIT() asm volatile("cp.async.commit_group;" ::: "memory")
#define CP_WAIT1()  asm volatile("cp.async.wait_group 1;" ::: "memory")
#define CP_WAIT0()  asm volatile("cp.async.wait_group 0;" ::: "memory")

__device__ __forceinline__ void ldsm4(uint32_t r[4], uint32_t addr) {
    asm volatile("ldmatrix.sync.aligned.m8n8.x4.shared.b16 {%0,%1,%2,%3}, [%4];"
                 : "=r"(r[0]), "=r"(r[1]), "=r"(r[2]), "=r"(r[3]) : "r"(addr));
}
__device__ __forceinline__ void mma16816(float d[4], const uint32_t a[4],
                                         const uint32_t b[2]) {
    asm volatile(
        "mma.sync.aligned.m16n8k16.row.col.f32.f16.f16.f32 "
        "{%0,%1,%2,%3}, {%4,%5,%6,%7}, {%8,%9}, {%0,%1,%2,%3};"
        : "+f"(d[0]), "+f"(d[1]), "+f"(d[2]), "+f"(d[3])
        : "r"(a[0]), "r"(a[1]), "r"(a[2]), "r"(a[3]), "r"(b[0]), "r"(b[1]));
}
__device__ __forceinline__ unsigned pack2h(__half a, __half b) {
    return (unsigned)__half_as_ushort(a) | ((unsigned)__half_as_ushort(b) << 16);
}

// ---------------- ONE prep kernel: group (block 0) | prep_w | prep_g -------
// grid: [0] group, [1..2048] prep_w, [2049..3072] prep_g
#define PREPW_FIRST 1
#define PREPG_FIRST 2049
#define PREP_GRID   3073

__global__ void __launch_bounds__(256)
prep_all(const int* __restrict__ tv32, const float* __restrict__ g,
         const float* __restrict__ W1)
{
    const int bx = blockIdx.x;
    const int tid = threadIdx.x;

    if (bx == 0) {
        // ---- grouping: warp-replicated counters (8 warps x 32 tissues) ----
        __shared__ int s_is64;
        __shared__ int cnt[8][NT];
        __shared__ int cur[8][NT];
        __shared__ int warpor[8];
        const int wgrp = tid >> 5;

        ((int*)cnt)[tid] = 0;

        int acc = 0;
        for (int i = tid; i < NB / 2; i += 256) acc |= tv32[2 * i + 1];
#pragma unroll
        for (int o = 16; o; o >>= 1) acc |= __shfl_xor_sync(0xFFFFFFFF, acc, o);
        if ((tid & 31) == 0) warpor[wgrp] = acc;
        __syncthreads();
        if (tid == 0) {
            int a = 0;
            for (int i = 0; i < 8; i++) a |= warpor[i];
            s_is64 = (a == 0);
        }
        __syncthreads();
        const int is64 = s_is64;

        // hist into this warp's private counter row
        for (int i = tid; i < NB; i += 256) {
            int t = is64 ? (int)((const long long*)tv32)[i] : tv32[i];
            atomicAdd(&cnt[wgrp][t], 1);
        }
        __syncthreads();
        if (tid == 0) {
            int off = 0, nt = 0;
            for (int t = 0; t < NT; t++) {
                int c = 0;
#pragma unroll
                for (int w = 0; w < 8; w++) c += cnt[w][t];
                int bgs = off;
#pragma unroll
                for (int w = 0; w < 8; w++) { cur[w][t] = bgs; bgs += cnt[w][t]; }
                for (int s = 0; s < c; s += TM) {
                    d_tile_tissue[nt] = t;
                    d_tile_start[nt]  = off + s;
                    d_tile_rows[nt]   = (c - s) < TM ? (c - s) : TM;
                    nt++;
                }
                off += c;
            }
            d_ntiles = nt;
        }
        __syncthreads();
        // scatter using per-warp cursors (same i -> same warp as hist pass)
        for (int i = tid; i < NB; i += 256) {
            int t = is64 ? (int)((const long long*)tv32)[i] : tv32[i];
            int p = atomicAdd(&cur[wgrp][t], 1);
            d_perm[p] = i;
        }
    } else if (bx < PREPG_FIRST) {
        // ---- W transpose + convert: one 64x64 chunk ----
        const int cb = bx - PREPW_FIRST;
        const int t  = cb >> 6;
        const int n0 = ((cb >> 3) & 7) * 64;
        const int k0 = (cb & 7) * 64;
        __shared__ float st[64][65];
        const size_t tb = (size_t)t * NE * NE;
#pragma unroll
        for (int rr = 0; rr < 4; rr++) {
            int idx = tid + rr * 256;
            int k = idx >> 4;
            int nqc = (idx & 15) << 2;
            float4 v = *(const float4*)(W1 + tb + (size_t)(k0 + k) * NE + n0 + nqc);
            st[nqc + 0][k] = v.x; st[nqc + 1][k] = v.y;
            st[nqc + 2][k] = v.z; st[nqc + 3][k] = v.w;
        }
        __syncthreads();
        {
            int n  = tid >> 2;
            int kq = (tid & 3) << 4;
            unsigned hw[8];
#pragma unroll
            for (int j = 0; j < 16; j += 2)
                hw[j >> 1] = pack2h(__float2half_rn(st[n][kq + j]),
                                    __float2half_rn(st[n][kq + j + 1]));
            size_t oo = tb + (size_t)(n0 + n) * NE + k0 + kq;
            *(uint4*)(d_WhT + oo)     = make_uint4(hw[0], hw[1], hw[2], hw[3]);
            *(uint4*)(d_WhT + oo + 8) = make_uint4(hw[4], hw[5], hw[6], hw[7]);
        }
    } else {
        // ---- g convert: 4 independent float4 per thread (MLP 4) ----
        const int base = (bx - PREPG_FIRST) * 1024 + tid;
        float4 v[4];
#pragma unroll
        for (int r = 0; r < 4; r++) v[r] = ((const float4*)g)[base + r * 256];
#pragma unroll
        for (int r = 0; r < 4; r++)
            ((uint2*)d_Gh)[base + r * 256] = make_uint2(
                pack2h(__float2half_rn(v[r].x), __float2half_rn(v[r].y)),
                pack2h(__float2half_rn(v[r].z), __float2half_rn(v[r].w)));
    }
}

// ---------------- mma.sync fused GEMM (M=128, N=64 per CTA, 256 thr) -------
// R8/R10-proven: K-tile 32, 16 stages, separate finale.
// stage buf: A 0..8K | B 8K..12K
#define BUFSZ   12288
#define NSTAGE  3
#define SM_RED  (NSTAGE * BUFSZ)                 // float red[128][2] = 1KB
#define SM_TOTAL (SM_RED + 1024)

__global__ void __launch_bounds__(256, 3)
gemm_mma(const float* __restrict__ b1g, const float* __restrict__ W2g)
{
    extern __shared__ char smem[];
    const uint32_t ST = smem_u32(smem);
    const int tid = threadIdx.x, lane = tid & 31, wid = tid >> 5;
    const int wm = wid & 3, wn = wid >> 2;

    const int b = blockIdx.x;
    const int tile = b >> 3, nq = b & 7;
    if (tile >= d_ntiles) return;
    const int t = d_tile_tissue[tile];
    const int start = d_tile_start[tile];
    const int rows  = d_tile_rows[tile];

    // A gmem: thread loads row arow (2 chunks)
    const int arow = tid >> 1;
    const int m = arow < rows ? arow : rows - 1;
    const __half* pA = d_Gh + (size_t)d_perm[start + m] * NE;
    // B gmem: thread loads row brow (1 chunk)
    const int brow = tid >> 2;
    const __half* pB = d_WhT + (size_t)t * NE * NE + (size_t)(nq * 64 + brow) * NE;

    // store-side addressing
    const uint32_t stA = ST + (uint32_t)arow * 64;
    const int swsA = (arow >> 1) & 3;
    const int cpA = (tid & 1) * 2;
    const uint32_t stB = ST + 8192u + (uint32_t)brow * 64;
    const int swsB = (brow >> 1) & 3;
    const int cB_st = tid & 3;

    // ldmatrix addressing (proven swizzle math)
    const int rA  = lane & 15;
    const int cbA = lane >> 4;
    const int swA = (rA >> 1) & 3;
    const uint32_t preA = (uint32_t)(wm * 32 + rA) * 64;
    const int rB  = (lane & 7) + ((lane >> 4) & 1) * 8;
    const int cbB = (lane >> 3) & 1;
    const int swB = ((lane & 7) >> 1) & 3;
    const uint32_t preB = 8192u + (uint32_t)(wn * 32 + rB) * 64;

    float acc[2][4][4];
#pragma unroll
    for (int mt = 0; mt < 2; mt++)
#pragma unroll
        for (int j = 0; j < 4; j++)
#pragma unroll
            for (int q = 0; q < 4; q++) acc[mt][j][q] = 0.f;

    auto stage_load = [&](int s) {
        const uint32_t off = (uint32_t)(s % NSTAGE) * BUFSZ;
        const int k0 = s * 32;
#pragma unroll
        for (int c = cpA; c < cpA + 2; c++)
            CP16(stA + off + (uint32_t)((c ^ swsA) << 4), pA + k0 + c * 8);
        CP16(stB + off + (uint32_t)((cB_st ^ swsB) << 4), pB + k0 + cB_st * 8);
    };

    // 3-stage prologue
    stage_load(0); CP_COMMIT();
    stage_load(1); CP_COMMIT();

    for (int s = 0; s < 16; s++) {
        if (s < 15) CP_WAIT1(); else CP_WAIT0();
        __syncthreads();               // publishes stage s; frees buffer (s+2)%3
        if (s < 14) { stage_load(s + 2); CP_COMMIT(); }

        const uint32_t bufA = ST + (uint32_t)(s % NSTAGE) * BUFSZ;
#pragma unroll
        for (int ks = 0; ks < 2; ks++) {
            uint32_t a[2][4];
            const uint32_t cA = (uint32_t)(((2 * ks + cbA) ^ swA) << 4);
#pragma unroll
            for (int mt = 0; mt < 2; mt++)
                ldsm4(a[mt], bufA + preA + mt * 1024 + cA);
            const uint32_t cB = (uint32_t)(((2 * ks + cbB) ^ swB) << 4);
#pragma unroll
            for (int g = 0; g < 2; g++) {
                uint32_t bh[4];
                ldsm4(bh, bufA + preB + (uint32_t)g * 1024 + cB);
#pragma unroll
                for (int mt = 0; mt < 2; mt++) {
                    mma16816(acc[mt][2 * g],     a[mt], bh);
                    mma16816(acc[mt][2 * g + 1], a[mt], bh + 2);
                }
            }
        }
    }

    // fused epilogue: +b1 -> gelu -> *W2 -> partial row sums
    float ya[2][2] = {{0.f, 0.f}, {0.f, 0.f}};
#pragma unroll
    for (int mt = 0; mt < 2; mt++)
#pragma unroll
        for (int j = 0; j < 4; j++) {
            const int n = nq * 64 + wn * 32 + (j >> 1) * 16 + (j & 1) * 8 + 2 * (lane & 3);
            const float b10 = __ldg(&b1g[t * NE + n]);
            const float b11 = __ldg(&b1g[t * NE + n + 1]);
            const float w20 = __ldg(&W2g[t * NE + n]);
            const float w21 = __ldg(&W2g[t * NE + n + 1]);
            float h0 = acc[mt][j][0] + b10;
            float h1 = acc[mt][j][1] + b11;
            float h2 = acc[mt][j][2] + b10;
            float h3 = acc[mt][j][3] + b11;
            const float K = 0.70710678118654752f;
            float g0 = 0.5f * h0 * (1.0f + erff(h0 * K));
            float g1 = 0.5f * h1 * (1.0f + erff(h1 * K));
            float g2 = 0.5f * h2 * (1.0f + erff(h2 * K));
            float g3 = 0.5f * h3 * (1.0f + erff(h3 * K));
            ya[mt][0] = fmaf(g0, w20, fmaf(g1, w21, ya[mt][0]));
            ya[mt][1] = fmaf(g2, w20, fmaf(g3, w21, ya[mt][1]));
        }

    float* red = (float*)(smem + SM_RED);   // [128][2]
#pragma unroll
    for (int mt = 0; mt < 2; mt++)
#pragma unroll
        for (int rr = 0; rr < 2; rr++) {
            float v = ya[mt][rr];
            v += __shfl_xor_sync(0xFFFFFFFF, v, 1);
            v += __shfl_xor_sync(0xFFFFFFFF, v, 2);
            if ((lane & 3) == 0) {
                int r = wm * 32 + mt * 16 + (lane >> 2) + rr * 8;
                red[r * 2 + wn] = v;
            }
        }
    __syncthreads();
    if (tid < TM)
        d_part[b * TM + tid] = red[tid * 2] + red[tid * 2 + 1];
}

// ---------------- finale: sum 8 partials + b2, softplus, scatter ----------------
__global__ void finale(const float* __restrict__ b2g, float* __restrict__ out) {
    const int tile = blockIdx.x;
    if (tile >= d_ntiles) return;
    const int tid = threadIdx.x;
    const int t = d_tile_tissue[tile];
    const int start = d_tile_start[tile];
    const int rows  = d_tile_rows[tile];
    if (tid < rows) {
        float s = 0.f;
#pragma unroll
        for (int q = 0; q < NQ; q++)
            s += d_part[(tile * NQ + q) * TM + tid];
        s += __ldg(&b2g[t]);
        float y = fmaxf(s, 0.f) + log1pf(expf(-fabsf(s)));
        out[d_perm[start + tid]] = y;
    }
}

// ---------------- launch ----------------
extern "C" void kernel_launch(void* const* d_in, const int* in_sizes, int n_in,
                              void* d_out, int out_size)
{
    const float* g  = (const float*)d_in[0];
    const void*  tv = d_in[1];
    const float* W1 = (const float*)d_in[2];
    const float* b1 = (const float*)d_in[3];
    const float* W2 = (const float*)d_in[4];
    const float* b2 = (const float*)d_in[5];
    float* out = (float*)d_out;

    cudaFuncSetAttribute(gemm_mma, cudaFuncAttributeMaxDynamicSharedMemorySize, SM_TOTAL);

    prep_all<<<PREP_GRID, 256>>>((const int*)tv, g, W1);
    gemm_mma<<<MAXCTAS, 256, SM_TOTAL>>>(b1, W2);
    finale<<<MAXTILES, TM>>>(b2, out);
}

// round 14
// speedup vs baseline: 1.3006x; 1.0358x over previous
#include <cuda_runtime.h>
#include <cuda_fp16.h>
#include <math.h>
#include <stdint.h>

#define NB 8192
#define NE 512
#define NT 32
#define TM 128
#define MAXTILES (NB/TM + NT)        // 96
#define NQ 8                         // N-chunks of 64 per tile
#define MAXCTAS (MAXTILES * NQ)      // 768

// ---------------- device scratch ----------------
__device__ int d_perm[NB];
__device__ int d_tile_tissue[MAXTILES];
__device__ int d_tile_start[MAXTILES];
__device__ int d_tile_rows[MAXTILES];
__device__ int d_ntiles;
__device__ float d_part[MAXCTAS * TM];

__device__ __half d_Gh[NB * NE];
__device__ __half d_Wn[(size_t)NT * NE * NE];    // [t][k][n] — natural layout
// ---------------- PTX helpers (sm_80-level) ----------------
__device__ __forceinline__ uint32_t smem_u32(const void* p) {
    uint32_t a;
    asm("{ .reg .u64 t; cvta.to.shared.u64 t, %1; cvt.u32.u64 %0, t; }"
        : "=r"(a) : "l"(p));
    return a;
}
#define CP16(dst, src) \
    asm volatile("cp.async.cg.shared.global [%0], [%1], 16;" \
                 :: "r"(dst), "l"(src) : "memory")
#define CP_COMMIT() asm volatile("cp.async.commit_group;" ::: "memory")
#define CP_WAIT1()  asm volatile("cp.async.wait_group 1;" ::: "memory")
#define CP_WAIT0()  asm volatile("cp.async.wait_group 0;" ::: "memory")

__device__ __forceinline__ void ldsm4(uint32_t r[4], uint32_t addr) {
    asm volatile("ldmatrix.sync.aligned.m8n8.x4.shared.b16 {%0,%1,%2,%3}, [%4];"
                 : "=r"(r[0]), "=r"(r[1]), "=r"(r[2]), "=r"(r[3]) : "r"(addr));
}
__device__ __forceinline__ void ldsm4t(uint32_t r[4], uint32_t addr) {
    asm volatile("ldmatrix.sync.aligned.m8n8.x4.trans.shared.b16 {%0,%1,%2,%3}, [%4];"
                 : "=r"(r[0]), "=r"(r[1]), "=r"(r[2]), "=r"(r[3]) : "r"(addr));
}
__device__ __forceinline__ void mma16816(float d[4], const uint32_t a[4],
                                         const uint32_t b[2]) {
    asm volatile(
        "mma.sync.aligned.m16n8k16.row.col.f32.f16.f16.f32 "
        "{%0,%1,%2,%3}, {%4,%5,%6,%7}, {%8,%9}, {%0,%1,%2,%3};"
        : "+f"(d[0]), "+f"(d[1]), "+f"(d[2]), "+f"(d[3])
        : "r"(a[0]), "r"(a[1]), "r"(a[2]), "r"(a[3]), "r"(b[0]), "r"(b[1]));
}
__device__ __forceinline__ unsigned pack2h(__half a, __half b) {
    return (unsigned)__half_as_ushort(a) | ((unsigned)__half_as_ushort(b) << 16);
}

// ---------------- ONE prep kernel: group (block 0) | conv_w | conv_g -------
// grid: [0] group, [1..2048] conv_w (streaming), [2049..3072] conv_g
#define PREPW_FIRST 1
#define PREPG_FIRST 2049
#define PREP_GRID   3073

__global__ void __launch_bounds__(256)
prep_all(const int* __restrict__ tv32, const float* __restrict__ g,
         const float* __restrict__ W1)
{
    const int bx = blockIdx.x;
    const int tid = threadIdx.x;

    if (bx == 0) {
        // ---- grouping: warp-replicated counters (8 warps x 32 tissues) ----
        __shared__ int s_is64;
        __shared__ int cnt[8][NT];
        __shared__ int cur[8][NT];
        __shared__ int warpor[8];
        const int wgrp = tid >> 5;

        ((int*)cnt)[tid] = 0;

        int acc = 0;
        for (int i = tid; i < NB / 2; i += 256) acc |= tv32[2 * i + 1];
#pragma unroll
        for (int o = 16; o; o >>= 1) acc |= __shfl_xor_sync(0xFFFFFFFF, acc, o);
        if ((tid & 31) == 0) warpor[wgrp] = acc;
        __syncthreads();
        if (tid == 0) {
            int a = 0;
            for (int i = 0; i < 8; i++) a |= warpor[i];
            s_is64 = (a == 0);
        }
        __syncthreads();
        const int is64 = s_is64;

        for (int i = tid; i < NB; i += 256) {
            int t = is64 ? (int)((const long long*)tv32)[i] : tv32[i];
            atomicAdd(&cnt[wgrp][t], 1);
        }
        __syncthreads();
        if (tid == 0) {
            int off = 0, nt = 0;
            for (int t = 0; t < NT; t++) {
                int c = 0;
#pragma unroll
                for (int w = 0; w < 8; w++) c += cnt[w][t];
                int bgs = off;
#pragma unroll
                for (int w = 0; w < 8; w++) { cur[w][t] = bgs; bgs += cnt[w][t]; }
                for (int s = 0; s < c; s += TM) {
                    d_tile_tissue[nt] = t;
                    d_tile_start[nt]  = off + s;
                    d_tile_rows[nt]   = (c - s) < TM ? (c - s) : TM;
                    nt++;
                }
                off += c;
            }
            d_ntiles = nt;
        }
        __syncthreads();
        for (int i = tid; i < NB; i += 256) {
            int t = is64 ? (int)((const long long*)tv32)[i] : tv32[i];
            int p = atomicAdd(&cur[wgrp][t], 1);
            d_perm[p] = i;
        }
    } else if (bx < PREPG_FIRST) {
        // ---- W convert, layout preserved: pure streaming (MLP 4) ----
        const int base = (bx - PREPW_FIRST) * 1024 + tid;
        float4 v[4];
#pragma unroll
        for (int r = 0; r < 4; r++) v[r] = ((const float4*)W1)[base + r * 256];
#pragma unroll
        for (int r = 0; r < 4; r++)
            ((uint2*)d_Wn)[base + r * 256] = make_uint2(
                pack2h(__float2half_rn(v[r].x), __float2half_rn(v[r].y)),
                pack2h(__float2half_rn(v[r].z), __float2half_rn(v[r].w)));
    } else {
        // ---- g convert: streaming (MLP 4) ----
        const int base = (bx - PREPG_FIRST) * 1024 + tid;
        float4 v[4];
#pragma unroll
        for (int r = 0; r < 4; r++) v[r] = ((const float4*)g)[base + r * 256];
#pragma unroll
        for (int r = 0; r < 4; r++)
            ((uint2*)d_Gh)[base + r * 256] = make_uint2(
                pack2h(__float2half_rn(v[r].x), __float2half_rn(v[r].y)),
                pack2h(__float2half_rn(v[r].z), __float2half_rn(v[r].w)));
    }
}

// ---------------- mma.sync fused GEMM (M=128, N=64 per CTA, 256 thr) -------
// K-tile 32, 16 stages, separate finale.
// stage buf: A 0..8K | B 8K..12K  (B: 32 k-rows x 128B, chunk swizzle c^(k&7))
#define BUFSZ   12288
#define NSTAGE  3
#define SM_RED  (NSTAGE * BUFSZ)                 // float red[128][2] = 1KB
#define SM_TOTAL (SM_RED + 1024)

__global__ void __launch_bounds__(256, 3)
gemm_mma(const float* __restrict__ b1g, const float* __restrict__ W2g)
{
    extern __shared__ char smem[];
    const uint32_t ST = smem_u32(smem);
    const int tid = threadIdx.x, lane = tid & 31, wid = tid >> 5;
    const int wm = wid & 3, wn = wid >> 2;

    const int b = blockIdx.x;
    const int tile = b >> 3, nq = b & 7;
    if (tile >= d_ntiles) return;
    const int t = d_tile_tissue[tile];
    const int start = d_tile_start[tile];
    const int rows  = d_tile_rows[tile];

    // A gmem: thread loads row arow (2 chunks)
    const int arow = tid >> 1;
    const int m = arow < rows ? arow : rows - 1;
    const __half* pA = d_Gh + (size_t)d_perm[start + m] * NE;
    // B gmem: thread loads k-row k_st, chunk c_st (natural [k][n] layout)
    const int k_st = tid >> 3;
    const int c_st = tid & 7;
    const __half* pB = d_Wn + (size_t)t * NE * NE + (size_t)k_st * NE
                     + nq * 64 + c_st * 8;

    // store-side addressing
    const uint32_t stA = ST + (uint32_t)arow * 64;
    const int swsA = (arow >> 1) & 3;
    const int cpA = (tid & 1) * 2;
    const uint32_t stB = ST + 8192u + (uint32_t)k_st * 128
                       + (uint32_t)((c_st ^ (k_st & 7)) << 4);

    // ldmatrix addressing — A (proven), B (trans, k-row based)
    const int rA  = lane & 15;
    const int cbA = lane >> 4;
    const int swA = (rA >> 1) & 3;
    const uint32_t preA = (uint32_t)(wm * 32 + rA) * 64;
    const int rowB = lane & 15;            // k row within 16-block
    const int sw7  = rowB & 7;
    const int cnB  = wn * 4 + (lane >> 4); // base n-chunk for this lane
    const uint32_t preB = 8192u + (uint32_t)rowB * 128;

    float acc[2][4][4];
#pragma unroll
    for (int mt = 0; mt < 2; mt++)
#pragma unroll
        for (int j = 0; j < 4; j++)
#pragma unroll
            for (int q = 0; q < 4; q++) acc[mt][j][q] = 0.f;

    auto stage_load = [&](int s) {
        const uint32_t off = (uint32_t)(s % NSTAGE) * BUFSZ;
        const int k0 = s * 32;
#pragma unroll
        for (int c = cpA; c < cpA + 2; c++)
            CP16(stA + off + (uint32_t)((c ^ swsA) << 4), pA + k0 + c * 8);
        CP16(stB + off, pB + (size_t)k0 * NE);
    };

    // 3-stage prologue
    stage_load(0); CP_COMMIT();
    stage_load(1); CP_COMMIT();

    for (int s = 0; s < 16; s++) {
        if (s < 15) CP_WAIT1(); else CP_WAIT0();
        __syncthreads();               // publishes stage s; frees buffer (s+2)%3
        if (s < 14) { stage_load(s + 2); CP_COMMIT(); }

        const uint32_t buf = ST + (uint32_t)(s % NSTAGE) * BUFSZ;
#pragma unroll
        for (int ks = 0; ks < 2; ks++) {
            uint32_t a[2][4];
            const uint32_t cA = (uint32_t)(((2 * ks + cbA) ^ swA) << 4);
#pragma unroll
            for (int mt = 0; mt < 2; mt++)
                ldsm4(a[mt], buf + preA + mt * 1024 + cA);
            const uint32_t bB = buf + preB + (uint32_t)ks * 2048;
#pragma unroll
            for (int g = 0; g < 2; g++) {
                uint32_t bh[4];
                const uint32_t ch = (uint32_t)((cnB + g * 2) ^ sw7) << 4;
                ldsm4t(bh, bB + ch);
#pragma unroll
                for (int mt = 0; mt < 2; mt++) {
                    mma16816(acc[mt][2 * g],     a[mt], bh);
                    mma16816(acc[mt][2 * g + 1], a[mt], bh + 2);
                }
            }
        }
    }

    // fused epilogue: +b1 -> gelu -> *W2 -> partial row sums
    float ya[2][2] = {{0.f, 0.f}, {0.f, 0.f}};
#pragma unroll
    for (int mt = 0; mt < 2; mt++)
#pragma unroll
        for (int j = 0; j < 4; j++) {
            const int n = nq * 64 + wn * 32 + (j >> 1) * 16 + (j & 1) * 8 + 2 * (lane & 3);
            const float b10 = __ldg(&b1g[t * NE + n]);
            const float b11 = __ldg(&b1g[t * NE + n + 1]);
            const float w20 = __ldg(&W2g[t * NE + n]);
            const float w21 = __ldg(&W2g[t * NE + n + 1]);
            float h0 = acc[mt][j][0] + b10;
            float h1 = acc[mt][j][1] + b11;
            float h2 = acc[mt][j][2] + b10;
            float h3 = acc[mt][j][3] + b11;
            const float K = 0.70710678118654752f;
            float g0 = 0.5f * h0 * (1.0f + erff(h0 * K));
            float g1 = 0.5f * h1 * (1.0f + erff(h1 * K));
            float g2 = 0.5f * h2 * (1.0f + erff(h2 * K));
            float g3 = 0.5f * h3 * (1.0f + erff(h3 * K));
            ya[mt][0] = fmaf(g0, w20, fmaf(g1, w21, ya[mt][0]));
            ya[mt][1] = fmaf(g2, w20, fmaf(g3, w21, ya[mt][1]));
        }

    float* red = (float*)(smem + SM_RED);   // [128][2]
#pragma unroll
    for (int mt = 0; mt < 2; mt++)
#pragma unroll
        for (int rr = 0; rr < 2; rr++) {
            float v = ya[mt][rr];
            v += __shfl_xor_sync(0xFFFFFFFF, v, 1);
            v += __shfl_xor_sync(0xFFFFFFFF, v, 2);
            if ((lane & 3) == 0) {
                int r = wm * 32 + mt * 16 + (lane >> 2) + rr * 8;
                red[r * 2 + wn] = v;
            }
        }
    __syncthreads();
    if (tid < TM)
        d_part[b * TM + tid] = red[tid * 2] + red[tid * 2 + 1];
}

// ---------------- finale: sum 8 partials + b2, softplus, scatter ----------------
__global__ void finale(const float* __restrict__ b2g, float* __restrict__ out) {
    const int tile = blockIdx.x;
    if (tile >= d_ntiles) return;
    const int tid = threadIdx.x;
    const int t = d_tile_tissue[tile];
    const int start = d_tile_start[tile];
    const int rows  = d_tile_rows[tile];
    if (tid < rows) {
        float s = 0.f;
#pragma unroll
        for (int q = 0; q < NQ; q++)
            s += d_part[(tile * NQ + q) * TM + tid];
        s += __ldg(&b2g[t]);
        float y = fmaxf(s, 0.f) + log1pf(expf(-fabsf(s)));
        out[d_perm[start + tid]] = y;
    }
}

// ---------------- launch ----------------
extern "C" void kernel_launch(void* const* d_in, const int* in_sizes, int n_in,
                              void* d_out, int out_size)
{
    const float* g  = (const float*)d_in[0];
    const void*  tv = d_in[1];
    const float* W1 = (const float*)d_in[2];
    const float* b1 = (const float*)d_in[3];
    const float* W2 = (const float*)d_in[4];
    const float* b2 = (const float*)d_in[5];
    float* out = (float*)d_out;

    cudaFuncSetAttribute(gemm_mma, cudaFuncAttributeMaxDynamicSharedMemorySize, SM_TOTAL);

    prep_all<<<PREP_GRID, 256>>>((const int*)tv, g, W1);
    gemm_mma<<<MAXCTAS, 256, SM_TOTAL>>>(b1, W2);
    finale<<<MAXTILES, TM>>>(b2, out);
}

// round 15
// speedup vs baseline: 1.3425x; 1.0322x over previous
#include <cuda_runtime.h>
#include <cuda_fp16.h>
#include <math.h>
#include <stdint.h>

#define NB 8192
#define NE 512
#define NT 32
#define TM 128
#define MAXTILES (NB/TM + NT)        // 96
#define NQ 8                         // N-chunks of 64 per tile
#define MAXCTAS (MAXTILES * NQ)      // 768

// ---------------- device scratch ----------------
__device__ int d_perm[NB];
__device__ int d_tile_tissue[MAXTILES];
__device__ int d_tile_start[MAXTILES];
__device__ int d_tile_rows[MAXTILES];
__device__ int d_ntiles;
__device__ float d_part[MAXCTAS * TM];

__device__ __half d_Gh[NB * NE];
__device__ __half d_Wn[(size_t)NT * NE * NE];    // [t][k][n] — natural layout

// ---------------- PTX helpers (sm_80-level) ----------------
__device__ __forceinline__ uint32_t smem_u32(const void* p) {
    uint32_t a;
    asm("{ .reg .u64 t; cvta.to.shared.u64 t, %1; cvt.u32.u64 %0, t; }"
        : "=r"(a) : "l"(p));
    return a;
}
#define CP16(dst, src) \
    asm volatile("cp.async.cg.shared.global [%0], [%1], 16;" \
                 :: "r"(dst), "l"(src) : "memory")
#define CP_COMMIT() asm volatile("cp.async.commit_group;" ::: "memory")
#define CP_WAIT1()  asm volatile("cp.async.wait_group 1;" ::: "memory")
#define CP_WAIT0()  asm volatile("cp.async.wait_group 0;" ::: "memory")

__device__ __forceinline__ void ldsm4(uint32_t r[4], uint32_t addr) {
    asm volatile("ldmatrix.sync.aligned.m8n8.x4.shared.b16 {%0,%1,%2,%3}, [%4];"
                 : "=r"(r[0]), "=r"(r[1]), "=r"(r[2]), "=r"(r[3]) : "r"(addr));
}
__device__ __forceinline__ void ldsm4t(uint32_t r[4], uint32_t addr) {
    asm volatile("ldmatrix.sync.aligned.m8n8.x4.trans.shared.b16 {%0,%1,%2,%3}, [%4];"
                 : "=r"(r[0]), "=r"(r[1]), "=r"(r[2]), "=r"(r[3]) : "r"(addr));
}
__device__ __forceinline__ void mma16816(float d[4], const uint32_t a[4],
                                         const uint32_t b[2]) {
    asm volatile(
        "mma.sync.aligned.m16n8k16.row.col.f32.f16.f16.f32 "
        "{%0,%1,%2,%3}, {%4,%5,%6,%7}, {%8,%9}, {%0,%1,%2,%3};"
        : "+f"(d[0]), "+f"(d[1]), "+f"(d[2]), "+f"(d[3])
        : "r"(a[0]), "r"(a[1]), "r"(a[2]), "r"(a[3]), "r"(b[0]), "r"(b[1]));
}
__device__ __forceinline__ unsigned pack2h(__half a, __half b) {
    return (unsigned)__half_as_ushort(a) | ((unsigned)__half_as_ushort(b) << 16);
}

// ---------------- ONE prep kernel: group (block 0) | conv_w | conv_g -------
// grid: [0] group, [1..2048] conv_w (streaming), [2049..3072] conv_g
#define PREPW_FIRST 1
#define PREPG_FIRST 2049
#define PREP_GRID   3073

// load 16 tissue values starting at element `base` with batched int4 loads
__device__ __forceinline__ void load_tv16(const int* tv32, int base, int is64,
                                          int tv[16]) {
    if (is64) {
        int4 v[8];
#pragma unroll
        for (int r = 0; r < 8; r++)
            v[r] = ((const int4*)tv32)[(base >> 1) + r];
#pragma unroll
        for (int r = 0; r < 8; r++) { tv[2 * r] = v[r].x; tv[2 * r + 1] = v[r].z; }
    } else {
        int4 v[4];
#pragma unroll
        for (int r = 0; r < 4; r++)
            v[r] = ((const int4*)tv32)[(base >> 2) + r];
#pragma unroll
        for (int r = 0; r < 4; r++) {
            tv[4 * r] = v[r].x; tv[4 * r + 1] = v[r].y;
            tv[4 * r + 2] = v[r].z; tv[4 * r + 3] = v[r].w;
        }
    }
}

__global__ void __launch_bounds__(256)
prep_all(const int* __restrict__ tv32, const float* __restrict__ g,
         const float* __restrict__ W1)
{
    const int bx = blockIdx.x;
    const int tid = threadIdx.x;

    if (bx == 0) {
        // ---- grouping: batched loads (MLP 8) + warp-replicated counters ----
        __shared__ int s_is64;
        __shared__ int cnt[8][NT];
        __shared__ int cur[8][NT];
        __shared__ int warpor[8];
        const int wgrp = tid >> 5;

        ((int*)cnt)[tid] = 0;

        // detection: first 8192 int32 words (safe both layouts), 8 int4/thread
        int4 dv[8];
#pragma unroll
        for (int r = 0; r < 8; r++) dv[r] = ((const int4*)tv32)[tid + r * 256];
        int acc = 0;
#pragma unroll
        for (int r = 0; r < 8; r++) acc |= dv[r].y | dv[r].w;
#pragma unroll
        for (int o = 16; o; o >>= 1) acc |= __shfl_xor_sync(0xFFFFFFFF, acc, o);
        if ((tid & 31) == 0) warpor[wgrp] = acc;
        __syncthreads();
        if (tid == 0) {
            int a = 0;
            for (int i = 0; i < 8; i++) a |= warpor[i];
            s_is64 = (a == 0);
        }
        __syncthreads();
        const int is64 = s_is64;

        // hist: each thread owns 32 contiguous elements, 2 passes of 16
#pragma unroll
        for (int pass = 0; pass < 2; pass++) {
            int tv[16];
            const int base = tid * 32 + pass * 16;
            load_tv16(tv32, base, is64, tv);
#pragma unroll
            for (int j = 0; j < 16; j++) atomicAdd(&cnt[wgrp][tv[j]], 1);
        }
        __syncthreads();
        if (tid == 0) {
            int off = 0, nt = 0;
            for (int t = 0; t < NT; t++) {
                int c = 0;
#pragma unroll
                for (int w = 0; w < 8; w++) c += cnt[w][t];
                int bgs = off;
#pragma unroll
                for (int w = 0; w < 8; w++) { cur[w][t] = bgs; bgs += cnt[w][t]; }
                for (int s = 0; s < c; s += TM) {
                    d_tile_tissue[nt] = t;
                    d_tile_start[nt]  = off + s;
                    d_tile_rows[nt]   = (c - s) < TM ? (c - s) : TM;
                    nt++;
                }
                off += c;
            }
            d_ntiles = nt;
        }
        __syncthreads();
        // scatter: same element->warp mapping as hist
#pragma unroll
        for (int pass = 0; pass < 2; pass++) {
            int tv[16];
            const int base = tid * 32 + pass * 16;
            load_tv16(tv32, base, is64, tv);
#pragma unroll
            for (int j = 0; j < 16; j++) {
                int p = atomicAdd(&cur[wgrp][tv[j]], 1);
                d_perm[p] = base + j;
            }
        }
    } else if (bx < PREPG_FIRST) {
        // ---- W convert, layout preserved: pure streaming (MLP 4) ----
        const int base = (bx - PREPW_FIRST) * 1024 + tid;
        float4 v[4];
#pragma unroll
        for (int r = 0; r < 4; r++) v[r] = ((const float4*)W1)[base + r * 256];
#pragma unroll
        for (int r = 0; r < 4; r++)
            ((uint2*)d_Wn)[base + r * 256] = make_uint2(
                pack2h(__float2half_rn(v[r].x), __float2half_rn(v[r].y)),
                pack2h(__float2half_rn(v[r].z), __float2half_rn(v[r].w)));
    } else {
        // ---- g convert: streaming (MLP 4) ----
        const int base = (bx - PREPG_FIRST) * 1024 + tid;
        float4 v[4];
#pragma unroll
        for (int r = 0; r < 4; r++) v[r] = ((const float4*)g)[base + r * 256];
#pragma unroll
        for (int r = 0; r < 4; r++)
            ((uint2*)d_Gh)[base + r * 256] = make_uint2(
                pack2h(__float2half_rn(v[r].x), __float2half_rn(v[r].y)),
                pack2h(__float2half_rn(v[r].z), __float2half_rn(v[r].w)));
    }
}

// ---------------- mma.sync fused GEMM (M=128, N=64 per CTA, 256 thr) -------
// K-tile 32, 16 stages, separate finale.
// stage buf: A 0..8K | B 8K..12K  (B: 32 k-rows x 128B, chunk swizzle c^(k&7))
#define BUFSZ   12288
#define NSTAGE  3
#define SM_RED  (NSTAGE * BUFSZ)                 // float red[128][2] = 1KB
#define SM_TOTAL (SM_RED + 1024)

__global__ void __launch_bounds__(256, 3)
gemm_mma(const float* __restrict__ b1g, const float* __restrict__ W2g)
{
    extern __shared__ char smem[];
    const uint32_t ST = smem_u32(smem);
    const int tid = threadIdx.x, lane = tid & 31, wid = tid >> 5;
    const int wm = wid & 3, wn = wid >> 2;

    const int b = blockIdx.x;
    const int tile = b >> 3, nq = b & 7;
    if (tile >= d_ntiles) return;
    const int t = d_tile_tissue[tile];
    const int start = d_tile_start[tile];
    const int rows  = d_tile_rows[tile];

    // A gmem: thread loads row arow (2 chunks)
    const int arow = tid >> 1;
    const int m = arow < rows ? arow : rows - 1;
    const __half* pA = d_Gh + (size_t)d_perm[start + m] * NE;
    // B gmem: thread loads k-row k_st, chunk c_st (natural [k][n] layout)
    const int k_st = tid >> 3;
    const int c_st = tid & 7;
    const __half* pB = d_Wn + (size_t)t * NE * NE + (size_t)k_st * NE
                     + nq * 64 + c_st * 8;

    // store-side addressing
    const uint32_t stA = ST + (uint32_t)arow * 64;
    const int swsA = (arow >> 1) & 3;
    const int cpA = (tid & 1) * 2;
    const uint32_t stB = ST + 8192u + (uint32_t)k_st * 128
                       + (uint32_t)((c_st ^ (k_st & 7)) << 4);

    // ldmatrix addressing — A (proven), B (trans, k-row based)
    const int rA  = lane & 15;
    const int cbA = lane >> 4;
    const int swA = (rA >> 1) & 3;
    const uint32_t preA = (uint32_t)(wm * 32 + rA) * 64;
    const int rowB = lane & 15;            // k row within 16-block
    const int sw7  = rowB & 7;
    const int cnB  = wn * 4 + (lane >> 4); // base n-chunk for this lane
    const uint32_t preB = 8192u + (uint32_t)rowB * 128;

    float acc[2][4][4];
#pragma unroll
    for (int mt = 0; mt < 2; mt++)
#pragma unroll
        for (int j = 0; j < 4; j++)
#pragma unroll
            for (int q = 0; q < 4; q++) acc[mt][j][q] = 0.f;

    auto stage_load = [&](int s) {
        const uint32_t off = (uint32_t)(s % NSTAGE) * BUFSZ;
        const int k0 = s * 32;
#pragma unroll
        for (int c = cpA; c < cpA + 2; c++)
            CP16(stA + off + (uint32_t)((c ^ swsA) << 4), pA + k0 + c * 8);
        CP16(stB + off, pB + (size_t)k0 * NE);
    };

    // 3-stage prologue
    stage_load(0); CP_COMMIT();
    stage_load(1); CP_COMMIT();

    for (int s = 0; s < 16; s++) {
        if (s < 15) CP_WAIT1(); else CP_WAIT0();
        __syncthreads();               // publishes stage s; frees buffer (s+2)%3
        if (s < 14) { stage_load(s + 2); CP_COMMIT(); }

        const uint32_t buf = ST + (uint32_t)(s % NSTAGE) * BUFSZ;
#pragma unroll
        for (int ks = 0; ks < 2; ks++) {
            uint32_t a[2][4];
            const uint32_t cA = (uint32_t)(((2 * ks + cbA) ^ swA) << 4);
#pragma unroll
            for (int mt = 0; mt < 2; mt++)
                ldsm4(a[mt], buf + preA + mt * 1024 + cA);
            const uint32_t bB = buf + preB + (uint32_t)ks * 2048;
#pragma unroll
            for (int g = 0; g < 2; g++) {
                uint32_t bh[4];
                const uint32_t ch = (uint32_t)((cnB + g * 2) ^ sw7) << 4;
                ldsm4t(bh, bB + ch);
#pragma unroll
                for (int mt = 0; mt < 2; mt++) {
                    mma16816(acc[mt][2 * g],     a[mt], bh);
                    mma16816(acc[mt][2 * g + 1], a[mt], bh + 2);
                }
            }
        }
    }

    // fused epilogue: +b1 -> gelu -> *W2 -> partial row sums
    float ya[2][2] = {{0.f, 0.f}, {0.f, 0.f}};
#pragma unroll
    for (int mt = 0; mt < 2; mt++)
#pragma unroll
        for (int j = 0; j < 4; j++) {
            const int n = nq * 64 + wn * 32 + (j >> 1) * 16 + (j & 1) * 8 + 2 * (lane & 3);
            const float b10 = __ldg(&b1g[t * NE + n]);
            const float b11 = __ldg(&b1g[t * NE + n + 1]);
            const float w20 = __ldg(&W2g[t * NE + n]);
            const float w21 = __ldg(&W2g[t * NE + n + 1]);
            float h0 = acc[mt][j][0] + b10;
            float h1 = acc[mt][j][1] + b11;
            float h2 = acc[mt][j][2] + b10;
            float h3 = acc[mt][j][3] + b11;
            const float K = 0.70710678118654752f;
            float g0 = 0.5f * h0 * (1.0f + erff(h0 * K));
            float g1 = 0.5f * h1 * (1.0f + erff(h1 * K));
            float g2 = 0.5f * h2 * (1.0f + erff(h2 * K));
            float g3 = 0.5f * h3 * (1.0f + erff(h3 * K));
            ya[mt][0] = fmaf(g0, w20, fmaf(g1, w21, ya[mt][0]));
            ya[mt][1] = fmaf(g2, w20, fmaf(g3, w21, ya[mt][1]));
        }

    float* red = (float*)(smem + SM_RED);   // [128][2]
#pragma unroll
    for (int mt = 0; mt < 2; mt++)
#pragma unroll
        for (int rr = 0; rr < 2; rr++) {
            float v = ya[mt][rr];
            v += __shfl_xor_sync(0xFFFFFFFF, v, 1);
            v += __shfl_xor_sync(0xFFFFFFFF, v, 2);
            if ((lane & 3) == 0) {
                int r = wm * 32 + mt * 16 + (lane >> 2) + rr * 8;
                red[r * 2 + wn] = v;
            }
        }
    __syncthreads();
    if (tid < TM)
        d_part[b * TM + tid] = red[tid * 2] + red[tid * 2 + 1];
}

// ---------------- finale: sum 8 partials + b2, softplus, scatter ----------------
__global__ void finale(const float* __restrict__ b2g, float* __restrict__ out) {
    const int tile = blockIdx.x;
    if (tile >= d_ntiles) return;
    const int tid = threadIdx.x;
    const int t = d_tile_tissue[tile];
    const int start = d_tile_start[tile];
    const int rows  = d_tile_rows[tile];
    if (tid < rows) {
        float s = 0.f;
#pragma unroll
        for (int q = 0; q < NQ; q++)
            s += d_part[(tile * NQ + q) * TM + tid];
        s += __ldg(&b2g[t]);
        float y = fmaxf(s, 0.f) + log1pf(expf(-fabsf(s)));
        out[d_perm[start + tid]] = y;
    }
}

// ---------------- launch ----------------
extern "C" void kernel_launch(void* const* d_in, const int* in_sizes, int n_in,
                              void* d_out, int out_size)
{
    const float* g  = (const float*)d_in[0];
    const void*  tv = d_in[1];
    const float* W1 = (const float*)d_in[2];
    const float* b1 = (const float*)d_in[3];
    const float* W2 = (const float*)d_in[4];
    const float* b2 = (const float*)d_in[5];
    float* out = (float*)d_out;

    cudaFuncSetAttribute(gemm_mma, cudaFuncAttributeMaxDynamicSharedMemorySize, SM_TOTAL);

    prep_all<<<PREP_GRID, 256>>>((const int*)tv, g, W1);
    gemm_mma<<<MAXCTAS, 256, SM_TOTAL>>>(b1, W2);
    finale<<<MAXTILES, TM>>>(b2, out);
}

// round 16
// speedup vs baseline: 1.3443x; 1.0013x over previous
#include <cuda_runtime.h>
#include <cuda_fp16.h>
#include <math.h>
#include <stdint.h>

#define NB 8192
#define NE 512
#define NT 32
#define TM 128
#define MAXTILES (NB/TM + NT)        // 96
#define NQ 8                         // N-chunks of 64 per tile
#define MAXCTAS (MAXTILES * NQ)      // 768

// ---------------- device scratch ----------------
__device__ int d_perm[NB];
__device__ int d_tile_tissue[MAXTILES];
__device__ int d_tile_start[MAXTILES];
__device__ int d_tile_rows[MAXTILES];
__device__ int d_ntiles;
__device__ float d_part[MAXCTAS * TM];

__device__ __half d_Gh[NB * NE];
__device__ __half d_Wn[(size_t)NT * NE * NE];    // [t][k][n] — natural layout

// ---------------- PTX helpers (sm_80-level) ----------------
__device__ __forceinline__ uint32_t smem_u32(const void* p) {
    uint32_t a;
    asm("{ .reg .u64 t; cvta.to.shared.u64 t, %1; cvt.u32.u64 %0, t; }"
        : "=r"(a) : "l"(p));
    return a;
}
#define CP16(dst, src) \
    asm volatile("cp.async.cg.shared.global [%0], [%1], 16;" \
                 :: "r"(dst), "l"(src) : "memory")
#define CP_COMMIT() asm volatile("cp.async.commit_group;" ::: "memory")
#define CP_WAIT3()  asm volatile("cp.async.wait_group 3;" ::: "memory")
#define CP_WAIT0()  asm volatile("cp.async.wait_group 0;" ::: "memory")

__device__ __forceinline__ void ldsm4(uint32_t r[4], uint32_t addr) {
    asm volatile("ldmatrix.sync.aligned.m8n8.x4.shared.b16 {%0,%1,%2,%3}, [%4];"
                 : "=r"(r[0]), "=r"(r[1]), "=r"(r[2]), "=r"(r[3]) : "r"(addr));
}
__device__ __forceinline__ void ldsm4t(uint32_t r[4], uint32_t addr) {
    asm volatile("ldmatrix.sync.aligned.m8n8.x4.trans.shared.b16 {%0,%1,%2,%3}, [%4];"
                 : "=r"(r[0]), "=r"(r[1]), "=r"(r[2]), "=r"(r[3]) : "r"(addr));
}
__device__ __forceinline__ void mma16816(float d[4], const uint32_t a[4],
                                         const uint32_t b[2]) {
    asm volatile(
        "mma.sync.aligned.m16n8k16.row.col.f32.f16.f16.f32 "
        "{%0,%1,%2,%3}, {%4,%5,%6,%7}, {%8,%9}, {%0,%1,%2,%3};"
        : "+f"(d[0]), "+f"(d[1]), "+f"(d[2]), "+f"(d[3])
        : "r"(a[0]), "r"(a[1]), "r"(a[2]), "r"(a[3]), "r"(b[0]), "r"(b[1]));
}
__device__ __forceinline__ unsigned pack2h(__half a, __half b) {
    return (unsigned)__half_as_ushort(a) | ((unsigned)__half_as_ushort(b) << 16);
}

// ---------------- ONE prep kernel: group (block 0) | conv_w | conv_g -------
// grid: [0] group, [1..1024] conv_w (MLP 8), [1025..1536] conv_g (MLP 8)
#define PREPW_FIRST 1
#define PREPG_FIRST 1025
#define PREP_GRID   1537

// load 16 tissue values starting at element `base` with batched int4 loads
__device__ __forceinline__ void load_tv16(const int* tv32, int base, int is64,
                                          int tv[16]) {
    if (is64) {
        int4 v[8];
#pragma unroll
        for (int r = 0; r < 8; r++)
            v[r] = ((const int4*)tv32)[(base >> 1) + r];
#pragma unroll
        for (int r = 0; r < 8; r++) { tv[2 * r] = v[r].x; tv[2 * r + 1] = v[r].z; }
    } else {
        int4 v[4];
#pragma unroll
        for (int r = 0; r < 4; r++)
            v[r] = ((const int4*)tv32)[(base >> 2) + r];
#pragma unroll
        for (int r = 0; r < 4; r++) {
            tv[4 * r] = v[r].x; tv[4 * r + 1] = v[r].y;
            tv[4 * r + 2] = v[r].z; tv[4 * r + 3] = v[r].w;
        }
    }
}

__device__ __forceinline__ void conv8(const float4* __restrict__ src,
                                      uint2* __restrict__ dst, int base) {
    float4 v[8];
#pragma unroll
    for (int r = 0; r < 8; r++) v[r] = src[base + r * 256];
#pragma unroll
    for (int r = 0; r < 8; r++)
        dst[base + r * 256] = make_uint2(
            pack2h(__float2half_rn(v[r].x), __float2half_rn(v[r].y)),
            pack2h(__float2half_rn(v[r].z), __float2half_rn(v[r].w)));
}

__global__ void __launch_bounds__(256)
prep_all(const int* __restrict__ tv32, const float* __restrict__ g,
         const float* __restrict__ W1)
{
    const int bx = blockIdx.x;
    const int tid = threadIdx.x;

    if (bx == 0) {
        // ---- grouping: batched loads (MLP 8) + warp-replicated counters ----
        __shared__ int s_is64;
        __shared__ int cnt[8][NT];
        __shared__ int cur[8][NT];
        __shared__ int warpor[8];
        const int wgrp = tid >> 5;

        ((int*)cnt)[tid] = 0;

        int4 dv[8];
#pragma unroll
        for (int r = 0; r < 8; r++) dv[r] = ((const int4*)tv32)[tid + r * 256];
        int acc = 0;
#pragma unroll
        for (int r = 0; r < 8; r++) acc |= dv[r].y | dv[r].w;
#pragma unroll
        for (int o = 16; o; o >>= 1) acc |= __shfl_xor_sync(0xFFFFFFFF, acc, o);
        if ((tid & 31) == 0) warpor[wgrp] = acc;
        __syncthreads();
        if (tid == 0) {
            int a = 0;
            for (int i = 0; i < 8; i++) a |= warpor[i];
            s_is64 = (a == 0);
        }
        __syncthreads();
        const int is64 = s_is64;

#pragma unroll
        for (int pass = 0; pass < 2; pass++) {
            int tv[16];
            const int base = tid * 32 + pass * 16;
            load_tv16(tv32, base, is64, tv);
#pragma unroll
            for (int j = 0; j < 16; j++) atomicAdd(&cnt[wgrp][tv[j]], 1);
        }
        __syncthreads();
        if (tid == 0) {
            int off = 0, nt = 0;
            for (int t = 0; t < NT; t++) {
                int c = 0;
#pragma unroll
                for (int w = 0; w < 8; w++) c += cnt[w][t];
                int bgs = off;
#pragma unroll
                for (int w = 0; w < 8; w++) { cur[w][t] = bgs; bgs += cnt[w][t]; }
                for (int s = 0; s < c; s += TM) {
                    d_tile_tissue[nt] = t;
                    d_tile_start[nt]  = off + s;
                    d_tile_rows[nt]   = (c - s) < TM ? (c - s) : TM;
                    nt++;
                }
                off += c;
            }
            d_ntiles = nt;
        }
        __syncthreads();
#pragma unroll
        for (int pass = 0; pass < 2; pass++) {
            int tv[16];
            const int base = tid * 32 + pass * 16;
            load_tv16(tv32, base, is64, tv);
#pragma unroll
            for (int j = 0; j < 16; j++) {
                int p = atomicAdd(&cur[wgrp][tv[j]], 1);
                d_perm[p] = base + j;
            }
        }
    } else if (bx < PREPG_FIRST) {
        // ---- W convert, layout preserved: MLP 8 streaming ----
        conv8((const float4*)W1, (uint2*)d_Wn,
              (bx - PREPW_FIRST) * 2048 + tid);
    } else {
        // ---- g convert: MLP 8 streaming ----
        conv8((const float4*)g, (uint2*)d_Gh,
              (bx - PREPG_FIRST) * 2048 + tid);
    }
}

// ---------------- mma.sync fused GEMM (M=128, N=64 per CTA, 256 thr) -------
// K-tile 32, 16 stages, 5-deep cp.async pipeline, separate finale.
// stage buf: A 0..8K | B 8K..12K  (B: 32 k-rows x 128B, chunk swizzle c^(k&7))
#define BUFSZ   12288
#define NSTAGE  5
#define SM_RED  (NSTAGE * BUFSZ)                 // float red[128][2] = 1KB
#define SM_TOTAL (SM_RED + 1024)

__global__ void __launch_bounds__(256, 3)
gemm_mma(const float* __restrict__ b1g, const float* __restrict__ W2g)
{
    extern __shared__ char smem[];
    const uint32_t ST = smem_u32(smem);
    const int tid = threadIdx.x, lane = tid & 31, wid = tid >> 5;
    const int wm = wid & 3, wn = wid >> 2;

    const int b = blockIdx.x;
    const int tile = b >> 3, nq = b & 7;
    if (tile >= d_ntiles) return;
    const int t = d_tile_tissue[tile];
    const int start = d_tile_start[tile];
    const int rows  = d_tile_rows[tile];

    // A gmem: thread loads row arow (2 chunks)
    const int arow = tid >> 1;
    const int m = arow < rows ? arow : rows - 1;
    const __half* pA = d_Gh + (size_t)d_perm[start + m] * NE;
    // B gmem: thread loads k-row k_st, chunk c_st (natural [k][n] layout)
    const int k_st = tid >> 3;
    const int c_st = tid & 7;
    const __half* pB = d_Wn + (size_t)t * NE * NE + (size_t)k_st * NE
                     + nq * 64 + c_st * 8;

    // store-side addressing
    const uint32_t stA = ST + (uint32_t)arow * 64;
    const int swsA = (arow >> 1) & 3;
    const int cpA = (tid & 1) * 2;
    const uint32_t stB = ST + 8192u + (uint32_t)k_st * 128
                       + (uint32_t)((c_st ^ (k_st & 7)) << 4);

    // ldmatrix addressing — A (proven), B (trans, k-row based)
    const int rA  = lane & 15;
    const int cbA = lane >> 4;
    const int swA = (rA >> 1) & 3;
    const uint32_t preA = (uint32_t)(wm * 32 + rA) * 64;
    const int rowB = lane & 15;            // k row within 16-block
    const int sw7  = rowB & 7;
    const int cnB  = wn * 4 + (lane >> 4); // base n-chunk for this lane
    const uint32_t preB = 8192u + (uint32_t)rowB * 128;

    float acc[2][4][4];
#pragma unroll
    for (int mt = 0; mt < 2; mt++)
#pragma unroll
        for (int j = 0; j < 4; j++)
#pragma unroll
            for (int q = 0; q < 4; q++) acc[mt][j][q] = 0.f;

    auto stage_load = [&](int s) {
        const uint32_t off = (uint32_t)(s % NSTAGE) * BUFSZ;
        const int k0 = s * 32;
#pragma unroll
        for (int c = cpA; c < cpA + 2; c++)
            CP16(stA + off + (uint32_t)((c ^ swsA) << 4), pA + k0 + c * 8);
        CP16(stB + off, pB + (size_t)k0 * NE);
    };

    // 5-stage prologue: prefetch stages 0..3
    stage_load(0); CP_COMMIT();
    stage_load(1); CP_COMMIT();
    stage_load(2); CP_COMMIT();
    stage_load(3); CP_COMMIT();

    for (int s = 0; s < 16; s++) {
        if (s < 13) CP_WAIT3(); else CP_WAIT0();
        __syncthreads();               // publishes stage s; frees buffer (s+4)%5
        if (s < 12) { stage_load(s + 4); CP_COMMIT(); }

        const uint32_t buf = ST + (uint32_t)(s % NSTAGE) * BUFSZ;
#pragma unroll
        for (int ks = 0; ks < 2; ks++) {
            uint32_t a[2][4];
            const uint32_t cA = (uint32_t)(((2 * ks + cbA) ^ swA) << 4);
#pragma unroll
            for (int mt = 0; mt < 2; mt++)
                ldsm4(a[mt], buf + preA + mt * 1024 + cA);
            const uint32_t bB = buf + preB + (uint32_t)ks * 2048;
#pragma unroll
            for (int g = 0; g < 2; g++) {
                uint32_t bh[4];
                const uint32_t ch = (uint32_t)((cnB + g * 2) ^ sw7) << 4;
                ldsm4t(bh, bB + ch);
#pragma unroll
                for (int mt = 0; mt < 2; mt++) {
                    mma16816(acc[mt][2 * g],     a[mt], bh);
                    mma16816(acc[mt][2 * g + 1], a[mt], bh + 2);
                }
            }
        }
    }

    // fused epilogue: +b1 -> gelu -> *W2 -> partial row sums
    float ya[2][2] = {{0.f, 0.f}, {0.f, 0.f}};
#pragma unroll
    for (int mt = 0; mt < 2; mt++)
#pragma unroll
        for (int j = 0; j < 4; j++) {
            const int n = nq * 64 + wn * 32 + (j >> 1) * 16 + (j & 1) * 8 + 2 * (lane & 3);
            const float b10 = __ldg(&b1g[t * NE + n]);
            const float b11 = __ldg(&b1g[t * NE + n + 1]);
            const float w20 = __ldg(&W2g[t * NE + n]);
            const float w21 = __ldg(&W2g[t * NE + n + 1]);
            float h0 = acc[mt][j][0] + b10;
            float h1 = acc[mt][j][1] + b11;
            float h2 = acc[mt][j][2] + b10;
            float h3 = acc[mt][j][3] + b11;
            const float K = 0.70710678118654752f;
            float g0 = 0.5f * h0 * (1.0f + erff(h0 * K));
            float g1 = 0.5f * h1 * (1.0f + erff(h1 * K));
            float g2 = 0.5f * h2 * (1.0f + erff(h2 * K));
            float g3 = 0.5f * h3 * (1.0f + erff(h3 * K));
            ya[mt][0] = fmaf(g0, w20, fmaf(g1, w21, ya[mt][0]));
            ya[mt][1] = fmaf(g2, w20, fmaf(g3, w21, ya[mt][1]));
        }

    float* red = (float*)(smem + SM_RED);   // [128][2]
#pragma unroll
    for (int mt = 0; mt < 2; mt++)
#pragma unroll
        for (int rr = 0; rr < 2; rr++) {
            float v = ya[mt][rr];
            v += __shfl_xor_sync(0xFFFFFFFF, v, 1);
            v += __shfl_xor_sync(0xFFFFFFFF, v, 2);
            if ((lane & 3) == 0) {
                int r = wm * 32 + mt * 16 + (lane >> 2) + rr * 8;
                red[r * 2 + wn] = v;
            }
        }
    __syncthreads();
    if (tid < TM)
        d_part[b * TM + tid] = red[tid * 2] + red[tid * 2 + 1];
}

// ---------------- finale: sum 8 partials + b2, softplus, scatter ----------------
__global__ void finale(const float* __restrict__ b2g, float* __restrict__ out) {
    const int tile = blockIdx.x;
    if (tile >= d_ntiles) return;
    const int tid = threadIdx.x;
    const int t = d_tile_tissue[tile];
    const int start = d_tile_start[tile];
    const int rows  = d_tile_rows[tile];
    if (tid < rows) {
        float s = 0.f;
#pragma unroll
        for (int q = 0; q < NQ; q++)
            s += d_part[(tile * NQ + q) * TM + tid];
        s += __ldg(&b2g[t]);
        float y = fmaxf(s, 0.f) + log1pf(expf(-fabsf(s)));
        out[d_perm[start + tid]] = y;
    }
}

// ---------------- launch ----------------
extern "C" void kernel_launch(void* const* d_in, const int* in_sizes, int n_in,
                              void* d_out, int out_size)
{
    const float* g  = (const float*)d_in[0];
    const void*  tv = d_in[1];
    const float* W1 = (const float*)d_in[2];
    const float* b1 = (const float*)d_in[3];
    const float* W2 = (const float*)d_in[4];
    const float* b2 = (const float*)d_in[5];
    float* out = (float*)d_out;

    cudaFuncSetAttribute(gemm_mma, cudaFuncAttributeMaxDynamicSharedMemorySize, SM_TOTAL);

    prep_all<<<PREP_GRID, 256>>>((const int*)tv, g, W1);
    gemm_mma<<<MAXCTAS, 256, SM_TOTAL>>>(b1, W2);
    finale<<<MAXTILES, TM>>>(b2, out);
}

// round 17
// speedup vs baseline: 1.4058x; 1.0457x over previous
#include <cuda_runtime.h>
#include <cuda_fp16.h>
#include <math.h>
#include <stdint.h>

#define NB 8192
#define NE 512
#define NT 32
#define TM 128
#define MAXTILES (NB/TM + NT)        // 96
#define NQ 4                         // N-chunks of 128 per tile
#define MAXCTAS (MAXTILES * NQ)      // 384

// ---------------- device scratch ----------------
__device__ int d_perm[NB];
__device__ int d_tile_tissue[MAXTILES];
__device__ int d_tile_start[MAXTILES];
__device__ int d_tile_rows[MAXTILES];
__device__ int d_ntiles;
__device__ float d_part[MAXCTAS * TM];

__device__ __half d_Gh[NB * NE];
__device__ __half d_Wn[(size_t)NT * NE * NE];    // [t][k][n] — natural layout

// ---------------- PTX helpers (sm_80-level) ----------------
__device__ __forceinline__ uint32_t smem_u32(const void* p) {
    uint32_t a;
    asm("{ .reg .u64 t; cvta.to.shared.u64 t, %1; cvt.u32.u64 %0, t; }"
        : "=r"(a) : "l"(p));
    return a;
}
#define CP16(dst, src) \
    asm volatile("cp.async.cg.shared.global [%0], [%1], 16;" \
                 :: "r"(dst), "l"(src) : "memory")
#define CP_COMMIT() asm volatile("cp.async.commit_group;" ::: "memory")
#define CP_WAIT3()  asm volatile("cp.async.wait_group 3;" ::: "memory")
#define CP_WAIT0()  asm volatile("cp.async.wait_group 0;" ::: "memory")

__device__ __forceinline__ void ldsm4(uint32_t r[4], uint32_t addr) {
    asm volatile("ldmatrix.sync.aligned.m8n8.x4.shared.b16 {%0,%1,%2,%3}, [%4];"
                 : "=r"(r[0]), "=r"(r[1]), "=r"(r[2]), "=r"(r[3]) : "r"(addr));
}
__device__ __forceinline__ void ldsm4t(uint32_t r[4], uint32_t addr) {
    asm volatile("ldmatrix.sync.aligned.m8n8.x4.trans.shared.b16 {%0,%1,%2,%3}, [%4];"
                 : "=r"(r[0]), "=r"(r[1]), "=r"(r[2]), "=r"(r[3]) : "r"(addr));
}
__device__ __forceinline__ void mma16816(float d[4], const uint32_t a[4],
                                         const uint32_t b[2]) {
    asm volatile(
        "mma.sync.aligned.m16n8k16.row.col.f32.f16.f16.f32 "
        "{%0,%1,%2,%3}, {%4,%5,%6,%7}, {%8,%9}, {%0,%1,%2,%3};"
        : "+f"(d[0]), "+f"(d[1]), "+f"(d[2]), "+f"(d[3])
        : "r"(a[0]), "r"(a[1]), "r"(a[2]), "r"(a[3]), "r"(b[0]), "r"(b[1]));
}
__device__ __forceinline__ unsigned pack2h(__half a, __half b) {
    return (unsigned)__half_as_ushort(a) | ((unsigned)__half_as_ushort(b) << 16);
}

// ---------------- ONE prep kernel: group (block 0) | conv_w | conv_g -------
// grid: [0] group, [1..1024] conv_w (MLP 8), [1025..1536] conv_g (MLP 8)
#define PREPW_FIRST 1
#define PREPG_FIRST 1025
#define PREP_GRID   1537

// load 16 tissue values starting at element `base` with batched int4 loads
__device__ __forceinline__ void load_tv16(const int* tv32, int base, int is64,
                                          int tv[16]) {
    if (is64) {
        int4 v[8];
#pragma unroll
        for (int r = 0; r < 8; r++)
            v[r] = ((const int4*)tv32)[(base >> 1) + r];
#pragma unroll
        for (int r = 0; r < 8; r++) { tv[2 * r] = v[r].x; tv[2 * r + 1] = v[r].z; }
    } else {
        int4 v[4];
#pragma unroll
        for (int r = 0; r < 4; r++)
            v[r] = ((const int4*)tv32)[(base >> 2) + r];
#pragma unroll
        for (int r = 0; r < 4; r++) {
            tv[4 * r] = v[r].x; tv[4 * r + 1] = v[r].y;
            tv[4 * r + 2] = v[r].z; tv[4 * r + 3] = v[r].w;
        }
    }
}

__device__ __forceinline__ void conv8(const float4* __restrict__ src,
                                      uint2* __restrict__ dst, int base) {
    float4 v[8];
#pragma unroll
    for (int r = 0; r < 8; r++) v[r] = src[base + r * 256];
#pragma unroll
    for (int r = 0; r < 8; r++)
        dst[base + r * 256] = make_uint2(
            pack2h(__float2half_rn(v[r].x), __float2half_rn(v[r].y)),
            pack2h(__float2half_rn(v[r].z), __float2half_rn(v[r].w)));
}

__global__ void __launch_bounds__(256)
prep_all(const int* __restrict__ tv32, const float* __restrict__ g,
         const float* __restrict__ W1)
{
    const int bx = blockIdx.x;
    const int tid = threadIdx.x;

    if (bx == 0) {
        __shared__ int s_is64;
        __shared__ int cnt[8][NT];
        __shared__ int cur[8][NT];
        __shared__ int warpor[8];
        const int wgrp = tid >> 5;

        ((int*)cnt)[tid] = 0;

        int4 dv[8];
#pragma unroll
        for (int r = 0; r < 8; r++) dv[r] = ((const int4*)tv32)[tid + r * 256];
        int acc = 0;
#pragma unroll
        for (int r = 0; r < 8; r++) acc |= dv[r].y | dv[r].w;
#pragma unroll
        for (int o = 16; o; o >>= 1) acc |= __shfl_xor_sync(0xFFFFFFFF, acc, o);
        if ((tid & 31) == 0) warpor[wgrp] = acc;
        __syncthreads();
        if (tid == 0) {
            int a = 0;
            for (int i = 0; i < 8; i++) a |= warpor[i];
            s_is64 = (a == 0);
        }
        __syncthreads();
        const int is64 = s_is64;

#pragma unroll
        for (int pass = 0; pass < 2; pass++) {
            int tv[16];
            const int base = tid * 32 + pass * 16;
            load_tv16(tv32, base, is64, tv);
#pragma unroll
            for (int j = 0; j < 16; j++) atomicAdd(&cnt[wgrp][tv[j]], 1);
        }
        __syncthreads();
        if (tid == 0) {
            int off = 0, nt = 0;
            for (int t = 0; t < NT; t++) {
                int c = 0;
#pragma unroll
                for (int w = 0; w < 8; w++) c += cnt[w][t];
                int bgs = off;
#pragma unroll
                for (int w = 0; w < 8; w++) { cur[w][t] = bgs; bgs += cnt[w][t]; }
                for (int s = 0; s < c; s += TM) {
                    d_tile_tissue[nt] = t;
                    d_tile_start[nt]  = off + s;
                    d_tile_rows[nt]   = (c - s) < TM ? (c - s) : TM;
                    nt++;
                }
                off += c;
            }
            d_ntiles = nt;
        }
        __syncthreads();
#pragma unroll
        for (int pass = 0; pass < 2; pass++) {
            int tv[16];
            const int base = tid * 32 + pass * 16;
            load_tv16(tv32, base, is64, tv);
#pragma unroll
            for (int j = 0; j < 16; j++) {
                int p = atomicAdd(&cur[wgrp][tv[j]], 1);
                d_perm[p] = base + j;
            }
        }
    } else if (bx < PREPG_FIRST) {
        conv8((const float4*)W1, (uint2*)d_Wn,
              (bx - PREPW_FIRST) * 2048 + tid);
    } else {
        conv8((const float4*)g, (uint2*)d_Gh,
              (bx - PREPG_FIRST) * 2048 + tid);
    }
}

// ---------------- mma.sync fused GEMM (M=128, N=128 per CTA, 256 thr) ------
// K-tile 32, 16 stages, 5-deep cp.async pipeline, separate finale.
// stage buf: A 0..8K | B 8K..16K  (B: 32 k-rows x 256B, chunk swizzle c^(k&7))
#define BUFSZ   16384
#define NSTAGE  5
#define SM_RED  (NSTAGE * BUFSZ)                 // float red[128][2] = 1KB
#define SM_TOTAL (SM_RED + 1024)

__global__ void __launch_bounds__(256, 2)
gemm_mma(const float* __restrict__ b1g, const float* __restrict__ W2g)
{
    extern __shared__ char smem[];
    const uint32_t ST = smem_u32(smem);
    const int tid = threadIdx.x, lane = tid & 31, wid = tid >> 5;
    const int wm = wid & 3, wn = wid >> 2;

    const int b = blockIdx.x;
    const int tile = b >> 2, nq = b & 3;
    if (tile >= d_ntiles) return;
    const int t = d_tile_tissue[tile];
    const int start = d_tile_start[tile];
    const int rows  = d_tile_rows[tile];

    // A gmem: thread loads row arow (2 chunks)
    const int arow = tid >> 1;
    const int m = arow < rows ? arow : rows - 1;
    const __half* pA = d_Gh + (size_t)d_perm[start + m] * NE;
    // B gmem: thread loads k-row k_st, chunks c_st and c_st+8
    const int k_st = tid >> 3;
    const int c_st = tid & 7;
    const __half* pB = d_Wn + (size_t)t * NE * NE + (size_t)k_st * NE
                     + nq * 128 + c_st * 8;

    // store-side addressing
    const uint32_t stA = ST + (uint32_t)arow * 64;
    const int swsA = (arow >> 1) & 3;
    const int cpA = (tid & 1) * 2;
    const uint32_t stB = ST + 8192u + (uint32_t)k_st * 256
                       + (uint32_t)((c_st ^ (k_st & 7)) << 4);

    // ldmatrix addressing — A (proven), B (trans, k-row based)
    const int rA  = lane & 15;
    const int cbA = lane >> 4;
    const int swA = (rA >> 1) & 3;
    const uint32_t preA = (uint32_t)(wm * 32 + rA) * 64;
    const int rowB = lane & 15;            // k row within 16-block
    const int sw7  = rowB & 7;
    const int cnB  = wn * 8 + (lane >> 4); // base n-chunk for this lane
    const uint32_t preB = 8192u + (uint32_t)rowB * 256;

    float acc[2][8][4];
#pragma unroll
    for (int mt = 0; mt < 2; mt++)
#pragma unroll
        for (int j = 0; j < 8; j++)
#pragma unroll
            for (int q = 0; q < 4; q++) acc[mt][j][q] = 0.f;

    auto stage_load = [&](int s) {
        const uint32_t off = (uint32_t)(s % NSTAGE) * BUFSZ;
        const int k0 = s * 32;
#pragma unroll
        for (int c = cpA; c < cpA + 2; c++)
            CP16(stA + off + (uint32_t)((c ^ swsA) << 4), pA + k0 + c * 8);
        CP16(stB + off,       pB + (size_t)k0 * NE);
        CP16(stB + off + 128, pB + (size_t)k0 * NE + 64);
    };

    // 5-stage prologue: prefetch stages 0..3
    stage_load(0); CP_COMMIT();
    stage_load(1); CP_COMMIT();
    stage_load(2); CP_COMMIT();
    stage_load(3); CP_COMMIT();

    for (int s = 0; s < 16; s++) {
        if (s < 13) CP_WAIT3(); else CP_WAIT0();
        __syncthreads();               // publishes stage s; frees buffer (s+4)%5
        if (s < 12) { stage_load(s + 4); CP_COMMIT(); }

        const uint32_t buf = ST + (uint32_t)(s % NSTAGE) * BUFSZ;
#pragma unroll
        for (int ks = 0; ks < 2; ks++) {
            uint32_t a[2][4];
            const uint32_t cA = (uint32_t)(((2 * ks + cbA) ^ swA) << 4);
#pragma unroll
            for (int mt = 0; mt < 2; mt++)
                ldsm4(a[mt], buf + preA + mt * 1024 + cA);
            const uint32_t bB = buf + preB + (uint32_t)ks * 4096;
#pragma unroll
            for (int g = 0; g < 4; g++) {
                uint32_t bh[4];
                const uint32_t ch = (uint32_t)((cnB + g * 2) ^ sw7) << 4;
                ldsm4t(bh, bB + ch);
#pragma unroll
                for (int mt = 0; mt < 2; mt++) {
                    mma16816(acc[mt][2 * g],     a[mt], bh);
                    mma16816(acc[mt][2 * g + 1], a[mt], bh + 2);
                }
            }
        }
    }

    // fused epilogue: +b1 -> gelu -> *W2 -> partial row sums
    float ya[2][2] = {{0.f, 0.f}, {0.f, 0.f}};
#pragma unroll
    for (int mt = 0; mt < 2; mt++)
#pragma unroll
        for (int j = 0; j < 8; j++) {
            const int n = nq * 128 + wn * 64 + (j >> 1) * 16 + (j & 1) * 8 + 2 * (lane & 3);
            const float b10 = __ldg(&b1g[t * NE + n]);
            const float b11 = __ldg(&b1g[t * NE + n + 1]);
            const float w20 = __ldg(&W2g[t * NE + n]);
            const float w21 = __ldg(&W2g[t * NE + n + 1]);
            float h0 = acc[mt][j][0] + b10;
            float h1 = acc[mt][j][1] + b11;
            float h2 = acc[mt][j][2] + b10;
            float h3 = acc[mt][j][3] + b11;
            const float K = 0.70710678118654752f;
            float g0 = 0.5f * h0 * (1.0f + erff(h0 * K));
            float g1 = 0.5f * h1 * (1.0f + erff(h1 * K));
            float g2 = 0.5f * h2 * (1.0f + erff(h2 * K));
            float g3 = 0.5f * h3 * (1.0f + erff(h3 * K));
            ya[mt][0] = fmaf(g0, w20, fmaf(g1, w21, ya[mt][0]));
            ya[mt][1] = fmaf(g2, w20, fmaf(g3, w21, ya[mt][1]));
        }

    float* red = (float*)(smem + SM_RED);   // [128][2]
#pragma unroll
    for (int mt = 0; mt < 2; mt++)
#pragma unroll
        for (int rr = 0; rr < 2; rr++) {
            float v = ya[mt][rr];
            v += __shfl_xor_sync(0xFFFFFFFF, v, 1);
            v += __shfl_xor_sync(0xFFFFFFFF, v, 2);
            if ((lane & 3) == 0) {
                int r = wm * 32 + mt * 16 + (lane >> 2) + rr * 8;
                red[r * 2 + wn] = v;
            }
        }
    __syncthreads();
    if (tid < TM)
        d_part[b * TM + tid] = red[tid * 2] + red[tid * 2 + 1];
}

// ---------------- finale: sum 4 partials + b2, softplus, scatter ----------------
__global__ void finale(const float* __restrict__ b2g, float* __restrict__ out) {
    const int tile = blockIdx.x;
    if (tile >= d_ntiles) return;
    const int tid = threadIdx.x;
    const int t = d_tile_tissue[tile];
    const int start = d_tile_start[tile];
    const int rows  = d_tile_rows[tile];
    if (tid < rows) {
        float s = 0.f;
#pragma unroll
        for (int q = 0; q < NQ; q++)
            s += d_part[(tile * NQ + q) * TM + tid];
        s += __ldg(&b2g[t]);
        float y = fmaxf(s, 0.f) + log1pf(expf(-fabsf(s)));
        out[d_perm[start + tid]] = y;
    }
}

// ---------------- launch ----------------
extern "C" void kernel_launch(void* const* d_in, const int* in_sizes, int n_in,
                              void* d_out, int out_size)
{
    const float* g  = (const float*)d_in[0];
    const void*  tv = d_in[1];
    const float* W1 = (const float*)d_in[2];
    const float* b1 = (const float*)d_in[3];
    const float* W2 = (const float*)d_in[4];
    const float* b2 = (const float*)d_in[5];
    float* out = (float*)d_out;

    cudaFuncSetAttribute(gemm_mma, cudaFuncAttributeMaxDynamicSharedMemorySize, SM_TOTAL);

    prep_all<<<PREP_GRID, 256>>>((const int*)tv, g, W1);
    gemm_mma<<<MAXCTAS, 256, SM_TOTAL>>>(b1, W2);
    finale<<<MAXTILES, TM>>>(b2, out);
}